// round 1
// baseline (speedup 1.0000x reference)
#include <cuda_runtime.h>

// Problem constants
#define B_   1024
#define I_   256
#define J_   256
#define K_   64

// Tiling
#define TB   128          // b per CTA
#define TJ   64           // j per CTA
#define ISPL 4            // i-splits (partial sums)
#define IPC  (I_ / ISPL)  // 64 i per CTA
#define NTHR 512
#define SROW 65           // smem row stride in floats (pad: 65 ≡ 1 mod 32)

// Scratch (static __device__ — no allocations allowed)
__device__ int4   g_prep[I_ * B_];                 // {w0,w1,off0(float idx),off1}  4 MB
__device__ float4 g_part4[ISPL * B_ * J_ / 4];     // i-split partial sums          4 MB

// ---------------------------------------------------------------------------
// Prep: per (i,b) compute searchsorted interval + lerp weights.
// Layout [i][b] so the main kernel's per-b fetch is a single uniform LDG.128.
// ---------------------------------------------------------------------------
__global__ void prep_kernel(const float* __restrict__ x, const float* __restrict__ Xg) {
    __shared__ float Xs[K_];
    int t = threadIdx.x;
    if (t < K_) Xs[t] = Xg[t];
    __syncthreads();

    int g = blockIdx.x * blockDim.x + t;      // g = i*B + b, exactly I_*B_ threads
    int i = g >> 10;                          // / B_
    int b = g & (B_ - 1);
    float xv = x[b * I_ + i];

    float X0 = Xs[0];
    float h  = (Xs[K_ - 1] - X0) / (float)(K_ - 1);
    int k = (int)floorf((xv - X0) / h);
    k = min(max(k, 0), K_ - 2);
    // exact fixup against the true grid (matches searchsorted side="right",
    // idx clipped to [1, K-1], k = idx-1)
    while (k > 0 && xv < Xs[k]) --k;
    while (k < K_ - 2 && xv >= Xs[k + 1]) ++k;

    float x0 = Xs[k], x1 = Xs[k + 1];
    float tt = (xv - x0) / (x1 - x0);         // may lie outside [0,1]: extrapolation
    int off0 = k * SROW;                      // float index of row k0 in smem tile
    g_prep[g] = make_int4(__float_as_int(1.0f - tt), __float_as_int(tt),
                          off0, off0 + SROW);
}

// ---------------------------------------------------------------------------
// Main: grid (ISPL, J_/TJ, B_/TB) = (4,4,8) = 128 CTAs, 512 threads.
// Per i: stage Y[i, j0:j0+64, :] (contiguous 16KB) transposed to Ys[k][jj],
// then each warp processes 8 b's with warp-uniform k0 -> conflict-free LDS.
// ---------------------------------------------------------------------------
__global__ void __launch_bounds__(NTHR, 1)
main_kernel(const float* __restrict__ Y) {
    __shared__ float Ys[2][K_ * SROW];        // double buffer: 2 * 16640 B

    const int it = blockIdx.x;                // i-split   0..3
    const int jt = blockIdx.y;                // j-tile    0..3
    const int bt = blockIdx.z;                // b-tile    0..7
    const int i0 = it * IPC;
    const int j0 = jt * TJ;
    const int b0 = bt * TB;

    const int tid  = threadIdx.x;
    const int w    = tid >> 5;
    const int lane = tid & 31;
    const int bw   = b0 + w * 8;              // warp's first b (8 b per warp)

    float2 acc[8];
    #pragma unroll
    for (int q = 0; q < 8; ++q) acc[q] = make_float2(0.f, 0.f);

    // stage tile for index i into buffer buf (transposed, stride SROW)
    auto load_tile = [&](int i, int buf) {
        const float4* src = (const float4*)(Y + (size_t)i * (J_ * K_) + (size_t)j0 * K_);
        #pragma unroll
        for (int r = 0; r < 2; ++r) {
            int t4 = tid + r * NTHR;          // 0..1023 float4s
            float4 v = src[t4];               // coalesced
            int f  = t4 << 2;                 // base float index in [0,4096)
            int jj = f >> 6;                  // source row (j within tile)
            int k  = f & 63;                  // source col (multiple of 4)
            float* dst = &Ys[buf][0];
            dst[(k + 0) * SROW + jj] = v.x;   // 2-way bank conflict (pad 65)
            dst[(k + 1) * SROW + jj] = v.y;
            dst[(k + 2) * SROW + jj] = v.z;
            dst[(k + 3) * SROW + jj] = v.w;
        }
    };

    load_tile(i0, 0);
    for (int ii = 0; ii < IPC; ++ii) {
        __syncthreads();
        if (ii + 1 < IPC) load_tile(i0 + ii + 1, (ii + 1) & 1);

        const int4*  pr   = g_prep + (size_t)(i0 + ii) * B_ + bw;
        const float* base = &Ys[ii & 1][0];
        #pragma unroll
        for (int bb = 0; bb < 8; ++bb) {
            int4 p = pr[bb];                  // warp-uniform LDG.128 (broadcast)
            float w0 = __int_as_float(p.x);
            float w1 = __int_as_float(p.y);
            const float* r0 = base + p.z;     // row k0
            const float* r1 = base + p.w;     // row k0+1
            // banks (k0 + lane) mod 32: conflict-free
            float y0a = r0[lane], y0b = r0[lane + 32];
            float y1a = r1[lane], y1b = r1[lane + 32];
            acc[bb].x = fmaf(w0, y0a, fmaf(w1, y1a, acc[bb].x));
            acc[bb].y = fmaf(w0, y0b, fmaf(w1, y1b, acc[bb].y));
        }
    }

    // write partials (deterministic; per-it slice, no atomics)
    float* part = (float*)g_part4 + (size_t)it * (B_ * J_);
    #pragma unroll
    for (int bb = 0; bb < 8; ++bb) {
        float* o = part + (size_t)(bw + bb) * J_ + j0;
        o[lane]      = acc[bb].x;             // j = j0 + lane
        o[lane + 32] = acc[bb].y;             // j = j0 + lane + 32
    }
}

// ---------------------------------------------------------------------------
// Reduce the ISPL partials into the output.
// ---------------------------------------------------------------------------
__global__ void reduce_kernel(float* __restrict__ out) {
    int g = blockIdx.x * blockDim.x + threadIdx.x;   // over B*J/4 float4s
    const int stride = B_ * J_ / 4;
    float4 a = g_part4[g];
    float4 b = g_part4[g + stride];
    float4 c = g_part4[g + 2 * stride];
    float4 d = g_part4[g + 3 * stride];
    float4 r;
    r.x = (a.x + b.x) + (c.x + d.x);
    r.y = (a.y + b.y) + (c.y + d.y);
    r.z = (a.z + b.z) + (c.z + d.z);
    r.w = (a.w + b.w) + (c.w + d.w);
    ((float4*)out)[g] = r;
}

// ---------------------------------------------------------------------------
extern "C" void kernel_launch(void* const* d_in, const int* in_sizes, int n_in,
                              void* d_out, int out_size) {
    const float* x  = (const float*)d_in[0];   // [B, I]
    const float* Xg = (const float*)d_in[1];   // [K]
    const float* Y  = (const float*)d_in[2];   // [I, J, K]
    float* out = (float*)d_out;                // [B, J]

    prep_kernel<<<(I_ * B_) / 256, 256>>>(x, Xg);
    main_kernel<<<dim3(ISPL, J_ / TJ, B_ / TB), NTHR>>>(Y);
    reduce_kernel<<<(B_ * J_ / 4) / 256, 256>>>(out);
}